// round 1
// baseline (speedup 1.0000x reference)
#include <cuda_runtime.h>
#include <cuda_fp16.h>

#define E_ 8
#define D_ 1024
#define F_ 4096
#define T_ 8192
#define MAX_TILES 160

// ------------------- scratch (device globals; no runtime allocs) -------------------
__device__ __half g_w1h[(size_t)E_ * F_ * D_];      // 64 MB
__device__ __half g_w2h[(size_t)E_ * D_ * F_];      // 64 MB
__device__ __half g_hnh[(size_t)T_ * D_];           // 16 MB  (LN output, sorted order)
__device__ __half g_h1h[(size_t)T_ * F_];           // 64 MB  (relu(fc1), sorted order)
__device__ float  g_alpha[T_];
__device__ int    g_assign[T_];
__device__ int    g_srt[T_];                        // sorted idx -> original token
__device__ int    g_counts[E_];
__device__ int    g_offsets[E_];
__device__ int    g_cursor[E_];
__device__ int    g_tileE[MAX_TILES];
__device__ int    g_tileRow[MAX_TILES];
__device__ int    g_tileEnd[MAX_TILES];
__device__ int    g_numTiles;

// ------------------- init -------------------
__global__ void init_kernel() {
    int i = threadIdx.x;
    if (i < E_) g_counts[i] = 0;
}

// ------------------- fp32 -> fp16 weight conversion -------------------
__global__ void convert_kernel(const float* __restrict__ src, int which) {
    __half* dst = which ? g_w2h : g_w1h;
    size_t n4 = ((size_t)E_ * F_ * D_) / 4;
    size_t stride = (size_t)gridDim.x * blockDim.x;
    for (size_t i = (size_t)blockIdx.x * blockDim.x + threadIdx.x; i < n4; i += stride) {
        float4 v = ((const float4*)src)[i];
        __half2 a = __floats2half2_rn(v.x, v.y);
        __half2 b = __floats2half2_rn(v.z, v.w);
        ((__half2*)dst)[2 * i]     = a;
        ((__half2*)dst)[2 * i + 1] = b;
    }
}

// ------------------- routing: aff, argmax, alpha, counts -------------------
__global__ void routing_kernel(const float* __restrict__ x, const float* __restrict__ cent) {
    __shared__ float4 sc[E_][D_ / 4];
    int tid = threadIdx.x;
    for (int i = tid; i < E_ * D_ / 4; i += 256)
        ((float4*)&sc[0][0])[i] = ((const float4*)cent)[i];
    __syncthreads();

    int warp = tid >> 5, lane = tid & 31;
    int t = blockIdx.x * 8 + warp;
    const float4* xv = (const float4*)(x + (size_t)t * D_);

    float acc[E_];
#pragma unroll
    for (int e = 0; e < E_; e++) acc[e] = 0.f;
#pragma unroll
    for (int j = 0; j < 8; j++) {
        float4 v = xv[j * 32 + lane];
#pragma unroll
        for (int e = 0; e < E_; e++) {
            float4 c = sc[e][j * 32 + lane];
            acc[e] += v.x * c.x + v.y * c.y + v.z * c.z + v.w * c.w;
        }
    }
#pragma unroll
    for (int e = 0; e < E_; e++) {
#pragma unroll
        for (int off = 16; off > 0; off >>= 1)
            acc[e] += __shfl_xor_sync(0xFFFFFFFFu, acc[e], off);
    }
    if (lane == 0) {
        int best = 0; float bv = acc[0];
#pragma unroll
        for (int e = 1; e < E_; e++)
            if (acc[e] > bv) { bv = acc[e]; best = e; }
        g_assign[t] = best;
        g_alpha[t] = 1.f / (1.f + expf(-bv));
        atomicAdd(&g_counts[best], 1);
    }
}

// ------------------- scan: offsets + tile table -------------------
__global__ void scan_kernel() {
    if (threadIdx.x != 0) return;
    int off = 0;
    for (int e = 0; e < E_; e++) {
        g_offsets[e] = off;
        g_cursor[e] = off;
        off += g_counts[e];
    }
    int nt = 0;
    for (int e = 0; e < E_; e++) {
        int s0 = g_offsets[e];
        int s1 = s0 + g_counts[e];
        for (int r = s0; r < s1; r += 64) {
            g_tileE[nt]   = e;
            g_tileRow[nt] = r;
            g_tileEnd[nt] = s1;
            nt++;
        }
    }
    g_numTiles = nt;
}

// ------------------- scatter into sorted order -------------------
__global__ void scatter_kernel() {
    int t = blockIdx.x * blockDim.x + threadIdx.x;
    if (t >= T_) return;
    int e = g_assign[t];
    int s = atomicAdd(&g_cursor[e], 1);
    g_srt[s] = t;
}

// ------------------- layernorm (per sorted row) -> fp16 -------------------
__global__ void ln_kernel(const float* __restrict__ x,
                          const float* __restrict__ lng,
                          const float* __restrict__ lnb) {
    int s = blockIdx.x;
    int t = g_srt[s];
    int e = g_assign[t];
    int tid = threadIdx.x;  // 256 threads, 4 floats each

    float4 v = ((const float4*)(x + (size_t)t * D_))[tid];
    float sum = v.x + v.y + v.z + v.w;
    float sq  = v.x * v.x + v.y * v.y + v.z * v.z + v.w * v.w;

    __shared__ float red[2][8];
    int warp = tid >> 5, lane = tid & 31;
#pragma unroll
    for (int off = 16; off > 0; off >>= 1) {
        sum += __shfl_xor_sync(0xFFFFFFFFu, sum, off);
        sq  += __shfl_xor_sync(0xFFFFFFFFu, sq,  off);
    }
    if (lane == 0) { red[0][warp] = sum; red[1][warp] = sq; }
    __syncthreads();
    float tot = 0.f, totsq = 0.f;
#pragma unroll
    for (int w = 0; w < 8; w++) { tot += red[0][w]; totsq += red[1][w]; }
    float mu = tot * (1.f / D_);
    float var = totsq * (1.f / D_) - mu * mu;
    float rstd = rsqrtf(var + 1e-5f);

    float4 gg = ((const float4*)(lng + (size_t)e * D_))[tid];
    float4 bb = ((const float4*)(lnb + (size_t)e * D_))[tid];
    __half2 h0 = __floats2half2_rn((v.x - mu) * rstd * gg.x + bb.x,
                                   (v.y - mu) * rstd * gg.y + bb.y);
    __half2 h1 = __floats2half2_rn((v.z - mu) * rstd * gg.z + bb.z,
                                   (v.w - mu) * rstd * gg.w + bb.w);
    __half2* dst = (__half2*)(g_hnh + (size_t)s * D_);
    dst[2 * tid]     = h0;
    dst[2 * tid + 1] = h1;
}

// ------------------- mma helper -------------------
__device__ __forceinline__ void mma_16x8x16(float c[4], const unsigned a[4], const unsigned b[2]) {
    asm volatile(
        "mma.sync.aligned.m16n8k16.row.col.f32.f16.f16.f32 "
        "{%0,%1,%2,%3}, {%4,%5,%6,%7}, {%8,%9}, {%0,%1,%2,%3};"
        : "+f"(c[0]), "+f"(c[1]), "+f"(c[2]), "+f"(c[3])
        : "r"(a[0]), "r"(a[1]), "r"(a[2]), "r"(a[3]), "r"(b[0]), "r"(b[1]));
}

// ------------------- GEMM1: h1 = relu(hn @ w1[e]^T + b1[e]) -------------------
// grid: x = F/64 (=64), y = MAX_TILES ; 256 threads (8 warps, 2x4)
__global__ void gemm1_kernel(const float* __restrict__ b1) {
    int ti = blockIdx.y;
    if (ti >= g_numTiles) return;
    int e = g_tileE[ti], row0 = g_tileRow[ti], rend = g_tileEnd[ti];
    int n0 = blockIdx.x * 64;

    __shared__ __align__(16) __half As[64][40];
    __shared__ __align__(16) __half Bs[64][40];

    const __half* Bglob = g_w1h + (size_t)e * F_ * D_;

    int tid = threadIdx.x;
    int lrow = tid >> 2, lchunk = tid & 3;
    int warp = tid >> 5, lane = tid & 31;
    int g = lane >> 2, tg = lane & 3;
    int wm = warp >> 2, wn = warp & 3;

    float c[2][2][4];
#pragma unroll
    for (int mi = 0; mi < 2; mi++)
#pragma unroll
        for (int ni = 0; ni < 2; ni++)
#pragma unroll
            for (int k = 0; k < 4; k++) c[mi][ni][k] = 0.f;

    for (int k0 = 0; k0 < D_; k0 += 32) {
        int srow = row0 + lrow;
        uint4 av = (srow < rend)
                 ? *(const uint4*)(g_hnh + (size_t)srow * D_ + k0 + lchunk * 8)
                 : make_uint4(0u, 0u, 0u, 0u);
        *(uint4*)&As[lrow][lchunk * 8] = av;
        uint4 bv = *(const uint4*)(Bglob + (size_t)(n0 + lrow) * D_ + k0 + lchunk * 8);
        *(uint4*)&Bs[lrow][lchunk * 8] = bv;
        __syncthreads();

#pragma unroll
        for (int kk = 0; kk < 32; kk += 16) {
            unsigned a[2][4], b[2][2];
#pragma unroll
            for (int mi = 0; mi < 2; mi++) {
                int r = wm * 32 + mi * 16;
                a[mi][0] = *(const unsigned*)&As[r + g][kk + 2 * tg];
                a[mi][1] = *(const unsigned*)&As[r + g + 8][kk + 2 * tg];
                a[mi][2] = *(const unsigned*)&As[r + g][kk + 2 * tg + 8];
                a[mi][3] = *(const unsigned*)&As[r + g + 8][kk + 2 * tg + 8];
            }
#pragma unroll
            for (int ni = 0; ni < 2; ni++) {
                int cn = wn * 16 + ni * 8 + g;
                b[ni][0] = *(const unsigned*)&Bs[cn][kk + 2 * tg];
                b[ni][1] = *(const unsigned*)&Bs[cn][kk + 2 * tg + 8];
            }
#pragma unroll
            for (int mi = 0; mi < 2; mi++)
#pragma unroll
                for (int ni = 0; ni < 2; ni++)
                    mma_16x8x16(c[mi][ni], a[mi], b[ni]);
        }
        __syncthreads();
    }

#pragma unroll
    for (int mi = 0; mi < 2; mi++) {
#pragma unroll
        for (int ni = 0; ni < 2; ni++) {
            int r  = row0 + wm * 32 + mi * 16 + g;
            int cc = n0 + wn * 16 + ni * 8 + 2 * tg;
            float bi0 = b1[(size_t)e * F_ + cc];
            float bi1 = b1[(size_t)e * F_ + cc + 1];
            if (r < rend) {
                __half2 h = __floats2half2_rn(fmaxf(c[mi][ni][0] + bi0, 0.f),
                                              fmaxf(c[mi][ni][1] + bi1, 0.f));
                *(__half2*)(g_h1h + (size_t)r * F_ + cc) = h;
            }
            if (r + 8 < rend) {
                __half2 h = __floats2half2_rn(fmaxf(c[mi][ni][2] + bi0, 0.f),
                                              fmaxf(c[mi][ni][3] + bi1, 0.f));
                *(__half2*)(g_h1h + (size_t)(r + 8) * F_ + cc) = h;
            }
        }
    }
}

// ------------------- GEMM2: out[t] = x[t] + alpha*(h1 @ w2[e]^T + b2[e]) -------------------
// grid: x = D/64 (=16), y = MAX_TILES ; 256 threads
__global__ void gemm2_kernel(const float* __restrict__ x,
                             const float* __restrict__ b2,
                             float* __restrict__ out) {
    int ti = blockIdx.y;
    if (ti >= g_numTiles) return;
    int e = g_tileE[ti], row0 = g_tileRow[ti], rend = g_tileEnd[ti];
    int n0 = blockIdx.x * 64;

    __shared__ __align__(16) __half As[64][40];
    __shared__ __align__(16) __half Bs[64][40];

    const __half* Bglob = g_w2h + (size_t)e * D_ * F_;

    int tid = threadIdx.x;
    int lrow = tid >> 2, lchunk = tid & 3;
    int warp = tid >> 5, lane = tid & 31;
    int g = lane >> 2, tg = lane & 3;
    int wm = warp >> 2, wn = warp & 3;

    float c[2][2][4];
#pragma unroll
    for (int mi = 0; mi < 2; mi++)
#pragma unroll
        for (int ni = 0; ni < 2; ni++)
#pragma unroll
            for (int k = 0; k < 4; k++) c[mi][ni][k] = 0.f;

    for (int k0 = 0; k0 < F_; k0 += 32) {
        int srow = row0 + lrow;
        uint4 av = (srow < rend)
                 ? *(const uint4*)(g_h1h + (size_t)srow * F_ + k0 + lchunk * 8)
                 : make_uint4(0u, 0u, 0u, 0u);
        *(uint4*)&As[lrow][lchunk * 8] = av;
        uint4 bv = *(const uint4*)(Bglob + (size_t)(n0 + lrow) * F_ + k0 + lchunk * 8);
        *(uint4*)&Bs[lrow][lchunk * 8] = bv;
        __syncthreads();

#pragma unroll
        for (int kk = 0; kk < 32; kk += 16) {
            unsigned a[2][4], b[2][2];
#pragma unroll
            for (int mi = 0; mi < 2; mi++) {
                int r = wm * 32 + mi * 16;
                a[mi][0] = *(const unsigned*)&As[r + g][kk + 2 * tg];
                a[mi][1] = *(const unsigned*)&As[r + g + 8][kk + 2 * tg];
                a[mi][2] = *(const unsigned*)&As[r + g][kk + 2 * tg + 8];
                a[mi][3] = *(const unsigned*)&As[r + g + 8][kk + 2 * tg + 8];
            }
#pragma unroll
            for (int ni = 0; ni < 2; ni++) {
                int cn = wn * 16 + ni * 8 + g;
                b[ni][0] = *(const unsigned*)&Bs[cn][kk + 2 * tg];
                b[ni][1] = *(const unsigned*)&Bs[cn][kk + 2 * tg + 8];
            }
#pragma unroll
            for (int mi = 0; mi < 2; mi++)
#pragma unroll
                for (int ni = 0; ni < 2; ni++)
                    mma_16x8x16(c[mi][ni], a[mi], b[ni]);
        }
        __syncthreads();
    }

#pragma unroll
    for (int mi = 0; mi < 2; mi++) {
#pragma unroll
        for (int ni = 0; ni < 2; ni++) {
            int r  = row0 + wm * 32 + mi * 16 + g;
            int cc = n0 + wn * 16 + ni * 8 + 2 * tg;
            float bi0 = b2[(size_t)e * D_ + cc];
            float bi1 = b2[(size_t)e * D_ + cc + 1];
            if (r < rend) {
                int t = g_srt[r];
                float al = g_alpha[t];
                float2 xv = *(const float2*)(x + (size_t)t * D_ + cc);
                float2 o;
                o.x = xv.x + al * (c[mi][ni][0] + bi0);
                o.y = xv.y + al * (c[mi][ni][1] + bi1);
                *(float2*)(out + (size_t)t * D_ + cc) = o;
            }
            if (r + 8 < rend) {
                int t = g_srt[r + 8];
                float al = g_alpha[t];
                float2 xv = *(const float2*)(x + (size_t)t * D_ + cc);
                float2 o;
                o.x = xv.x + al * (c[mi][ni][2] + bi0);
                o.y = xv.y + al * (c[mi][ni][3] + bi1);
                *(float2*)(out + (size_t)t * D_ + cc) = o;
            }
        }
    }
}

// ------------------- launch -------------------
extern "C" void kernel_launch(void* const* d_in, const int* in_sizes, int n_in,
                              void* d_out, int out_size) {
    const float* x    = (const float*)d_in[0];
    const float* cent = (const float*)d_in[1];
    const float* lng  = (const float*)d_in[2];
    const float* lnb  = (const float*)d_in[3];
    const float* w1   = (const float*)d_in[4];
    const float* b1   = (const float*)d_in[5];
    const float* w2   = (const float*)d_in[6];
    const float* b2   = (const float*)d_in[7];
    float* out = (float*)d_out;

    init_kernel<<<1, 32>>>();
    convert_kernel<<<4096, 256>>>(w1, 0);
    convert_kernel<<<4096, 256>>>(w2, 1);
    routing_kernel<<<T_ / 8, 256>>>(x, cent);
    scan_kernel<<<1, 1>>>();
    scatter_kernel<<<T_ / 256, 256>>>();
    ln_kernel<<<T_, 256>>>(x, lng, lnb);
    gemm1_kernel<<<dim3(F_ / 64, MAX_TILES), 256>>>(b1);
    gemm2_kernel<<<dim3(D_ / 64, MAX_TILES), 256>>>(x, b2, out);
}

// round 2
// speedup vs baseline: 1.0760x; 1.0760x over previous
#include <cuda_runtime.h>
#include <cuda_fp16.h>

#define E_ 8
#define D_ 1024
#define F_ 4096
#define T_ 8192
#define TPAD (T_ + E_ * 128)     // 9216: per-expert 128-alignment padding
#define MAX_TILES 80

// ------------------- scratch (device globals; no runtime allocs) -------------------
__device__ __half g_w1h[(size_t)E_ * F_ * D_];      // 64 MB
__device__ __half g_w2h[(size_t)E_ * D_ * F_];      // 64 MB
__device__ __half g_hnh[(size_t)TPAD * D_];         // 18 MB  (LN output, sorted-padded)
__device__ __half g_h1h[(size_t)TPAD * F_];         // 72 MB  (relu(fc1), sorted-padded)
__device__ float  g_alpha[T_];
__device__ int    g_assign[T_];
__device__ int    g_srt[TPAD];                      // sorted idx -> original token
__device__ int    g_pos[T_];                        // token -> sorted idx
__device__ int    g_counts[E_];
__device__ int    g_offsets[E_];
__device__ int    g_cursor[E_];
__device__ int    g_tileE[MAX_TILES];
__device__ int    g_tileRow[MAX_TILES];
__device__ int    g_tileEnd[MAX_TILES];
__device__ int    g_numTiles;

// ------------------- small helpers -------------------
__device__ __forceinline__ unsigned smem_u32(const void* p) {
    return (unsigned)__cvta_generic_to_shared(p);
}
__device__ __forceinline__ void cp16(unsigned dst, const void* src, bool pred) {
    asm volatile("cp.async.cg.shared.global [%0], [%1], 16, %2;\n"
                 :: "r"(dst), "l"(src), "r"(pred ? 16 : 0));
}
__device__ __forceinline__ void cp_commit() { asm volatile("cp.async.commit_group;\n"); }
template <int N>
__device__ __forceinline__ void cp_wait() { asm volatile("cp.async.wait_group %0;\n" :: "n"(N)); }

__device__ __forceinline__ void mma_16x8x16(float c[4], const unsigned a[4], const unsigned b[2]) {
    asm volatile(
        "mma.sync.aligned.m16n8k16.row.col.f32.f16.f16.f32 "
        "{%0,%1,%2,%3}, {%4,%5,%6,%7}, {%8,%9}, {%0,%1,%2,%3};"
        : "+f"(c[0]), "+f"(c[1]), "+f"(c[2]), "+f"(c[3])
        : "r"(a[0]), "r"(a[1]), "r"(a[2]), "r"(a[3]), "r"(b[0]), "r"(b[1]));
}

// ------------------- init -------------------
__global__ void init_kernel() {
    int i = threadIdx.x;
    if (i < E_) g_counts[i] = 0;
}

// ------------------- fp32 -> fp16 weight conversion -------------------
__global__ void convert_kernel(const float* __restrict__ src, int which) {
    __half* dst = which ? g_w2h : g_w1h;
    size_t n4 = ((size_t)E_ * F_ * D_) / 4;
    size_t stride = (size_t)gridDim.x * blockDim.x;
    for (size_t i = (size_t)blockIdx.x * blockDim.x + threadIdx.x; i < n4; i += stride) {
        float4 v = ((const float4*)src)[i];
        ((__half2*)dst)[2 * i]     = __floats2half2_rn(v.x, v.y);
        ((__half2*)dst)[2 * i + 1] = __floats2half2_rn(v.z, v.w);
    }
}

// ------------------- routing: aff, argmax, alpha, counts -------------------
__global__ void routing_kernel(const float* __restrict__ x, const float* __restrict__ cent) {
    __shared__ float4 sc[E_][D_ / 4];
    int tid = threadIdx.x;
    for (int i = tid; i < E_ * D_ / 4; i += 256)
        ((float4*)&sc[0][0])[i] = ((const float4*)cent)[i];
    __syncthreads();

    int warp = tid >> 5, lane = tid & 31;
    int t = blockIdx.x * 8 + warp;
    const float4* xv = (const float4*)(x + (size_t)t * D_);

    float acc[E_];
#pragma unroll
    for (int e = 0; e < E_; e++) acc[e] = 0.f;
#pragma unroll
    for (int j = 0; j < 8; j++) {
        float4 v = xv[j * 32 + lane];
#pragma unroll
        for (int e = 0; e < E_; e++) {
            float4 c = sc[e][j * 32 + lane];
            acc[e] += v.x * c.x + v.y * c.y + v.z * c.z + v.w * c.w;
        }
    }
#pragma unroll
    for (int e = 0; e < E_; e++) {
#pragma unroll
        for (int off = 16; off > 0; off >>= 1)
            acc[e] += __shfl_xor_sync(0xFFFFFFFFu, acc[e], off);
    }
    if (lane == 0) {
        int best = 0; float bv = acc[0];
#pragma unroll
        for (int e = 1; e < E_; e++)
            if (acc[e] > bv) { bv = acc[e]; best = e; }
        g_assign[t] = best;
        g_alpha[t] = 1.f / (1.f + expf(-bv));
        atomicAdd(&g_counts[best], 1);
    }
}

// ------------------- scan: 128-aligned offsets + full-tile table -------------------
__global__ void scan_kernel() {
    if (threadIdx.x != 0) return;
    int off = 0, nt = 0;
    for (int e = 0; e < E_; e++) {
        g_offsets[e] = off;
        g_cursor[e] = off;
        int s1 = off + g_counts[e];
        for (int r = off; r < s1; r += 128) {
            g_tileE[nt]   = e;
            g_tileRow[nt] = r;
            g_tileEnd[nt] = s1;
            nt++;
        }
        off = (s1 + 127) & ~127;   // pad each expert to a multiple of 128
    }
    g_numTiles = nt;
}

// ------------------- scatter into sorted order -------------------
__global__ void scatter_kernel() {
    int t = blockIdx.x * blockDim.x + threadIdx.x;
    if (t >= T_) return;
    int e = g_assign[t];
    int s = atomicAdd(&g_cursor[e], 1);
    g_srt[s] = t;
    g_pos[t] = s;
}

// ------------------- layernorm (per token) -> fp16, sorted-padded layout -------------------
__global__ void ln_kernel(const float* __restrict__ x,
                          const float* __restrict__ lng,
                          const float* __restrict__ lnb) {
    int t = blockIdx.x;
    int s = g_pos[t];
    int e = g_assign[t];
    int tid = threadIdx.x;  // 256 threads, 4 floats each

    float4 v = ((const float4*)(x + (size_t)t * D_))[tid];
    float sum = v.x + v.y + v.z + v.w;
    float sq  = v.x * v.x + v.y * v.y + v.z * v.z + v.w * v.w;

    __shared__ float red[2][8];
    int warp = tid >> 5, lane = tid & 31;
#pragma unroll
    for (int off = 16; off > 0; off >>= 1) {
        sum += __shfl_xor_sync(0xFFFFFFFFu, sum, off);
        sq  += __shfl_xor_sync(0xFFFFFFFFu, sq,  off);
    }
    if (lane == 0) { red[0][warp] = sum; red[1][warp] = sq; }
    __syncthreads();
    float tot = 0.f, totsq = 0.f;
#pragma unroll
    for (int w = 0; w < 8; w++) { tot += red[0][w]; totsq += red[1][w]; }
    float mu = tot * (1.f / D_);
    float var = totsq * (1.f / D_) - mu * mu;
    float rstd = rsqrtf(var + 1e-5f);

    float4 gg = ((const float4*)(lng + (size_t)e * D_))[tid];
    float4 bb = ((const float4*)(lnb + (size_t)e * D_))[tid];
    __half2 h0 = __floats2half2_rn((v.x - mu) * rstd * gg.x + bb.x,
                                   (v.y - mu) * rstd * gg.y + bb.y);
    __half2 h1 = __floats2half2_rn((v.z - mu) * rstd * gg.z + bb.z,
                                   (v.w - mu) * rstd * gg.w + bb.w);
    __half2* dst = (__half2*)(g_hnh + (size_t)s * D_);
    dst[2 * tid]     = h0;
    dst[2 * tid + 1] = h1;
}

// ------------------- shared GEMM pieces -------------------
// Stage issue: load A tile [128 x 32] + B tile [128 x 32] (fp16, K-major rows)
template <int KDIM>
__device__ __forceinline__ void issue_tile(const __half* __restrict__ Ag,
                                           const __half* __restrict__ Bg,
                                           int k0, int rendRel,
                                           __half (*As)[40], __half (*Bs)[40], int tid) {
#pragma unroll
    for (int i = 0; i < 2; i++) {
        int lin = tid + i * 256;
        int row = lin >> 2, ch = lin & 3;
        cp16(smem_u32(&As[row][ch * 8]), Ag + (size_t)row * KDIM + k0 + ch * 8, row < rendRel);
        cp16(smem_u32(&Bs[row][ch * 8]), Bg + (size_t)row * KDIM + k0 + ch * 8, true);
    }
    cp_commit();
}

// Compute one 128x128x32 stage. Warp tile 32x64 (wm 0..3 rows, wn 0..1 cols).
__device__ __forceinline__ void compute_stage(const __half (*As)[40], const __half (*Bs)[40],
                                              float c[2][8][4],
                                              int wm, int wn, int g, int tg) {
#pragma unroll
    for (int kk = 0; kk < 32; kk += 16) {
        unsigned a[2][4];
#pragma unroll
        for (int mi = 0; mi < 2; mi++) {
            int r = wm * 32 + mi * 16 + g;
            a[mi][0] = *(const unsigned*)&As[r][kk + 2 * tg];
            a[mi][1] = *(const unsigned*)&As[r + 8][kk + 2 * tg];
            a[mi][2] = *(const unsigned*)&As[r][kk + 2 * tg + 8];
            a[mi][3] = *(const unsigned*)&As[r + 8][kk + 2 * tg + 8];
        }
#pragma unroll
        for (int ni = 0; ni < 8; ni++) {
            unsigned b[2];
            int cn = wn * 64 + ni * 8 + g;
            b[0] = *(const unsigned*)&Bs[cn][kk + 2 * tg];
            b[1] = *(const unsigned*)&Bs[cn][kk + 2 * tg + 8];
#pragma unroll
            for (int mi = 0; mi < 2; mi++)
                mma_16x8x16(c[mi][ni], a[mi], b);
        }
    }
}

// ------------------- GEMM1: h1 = relu(hn @ w1[e]^T + b1[e]) -------------------
// grid: (F/128, MAX_TILES), 256 threads
__global__ __launch_bounds__(256, 2) void gemm1_kernel(const float* __restrict__ b1) {
    int ti = blockIdx.y;
    if (ti >= g_numTiles) return;
    int e = g_tileE[ti], row0 = g_tileRow[ti], rend = g_tileEnd[ti];
    int n0 = blockIdx.x * 128;

    __shared__ __align__(16) __half As[2][128][40];
    __shared__ __align__(16) __half Bs[2][128][40];

    const __half* Ag = g_hnh + (size_t)row0 * D_;
    const __half* Bg = g_w1h + (size_t)e * F_ * D_ + (size_t)n0 * D_;
    int rendRel = rend - row0;

    int tid = threadIdx.x;
    int warp = tid >> 5, lane = tid & 31;
    int g = lane >> 2, tg = lane & 3;
    int wm = warp >> 1, wn = warp & 1;

    float c[2][8][4];
#pragma unroll
    for (int mi = 0; mi < 2; mi++)
#pragma unroll
        for (int ni = 0; ni < 8; ni++)
#pragma unroll
            for (int k = 0; k < 4; k++) c[mi][ni][k] = 0.f;

    constexpr int STEPS = D_ / 32;
    issue_tile<D_>(Ag, Bg, 0, rendRel, As[0], Bs[0], tid);
#pragma unroll 1
    for (int i = 0; i < STEPS; i++) {
        if (i + 1 < STEPS) {
            issue_tile<D_>(Ag, Bg, (i + 1) * 32, rendRel, As[(i + 1) & 1], Bs[(i + 1) & 1], tid);
            cp_wait<1>();
        } else {
            cp_wait<0>();
        }
        __syncthreads();
        compute_stage(As[i & 1], Bs[i & 1], c, wm, wn, g, tg);
        __syncthreads();
    }

    // epilogue: bias + relu -> fp16, unguarded (padded rows defined)
#pragma unroll
    for (int ni = 0; ni < 8; ni++) {
        int col = n0 + wn * 64 + ni * 8 + 2 * tg;
        float bi0 = b1[(size_t)e * F_ + col];
        float bi1 = b1[(size_t)e * F_ + col + 1];
#pragma unroll
        for (int mi = 0; mi < 2; mi++) {
            int r = row0 + wm * 32 + mi * 16 + g;
            *(__half2*)(g_h1h + (size_t)r * F_ + col) =
                __floats2half2_rn(fmaxf(c[mi][ni][0] + bi0, 0.f),
                                  fmaxf(c[mi][ni][1] + bi1, 0.f));
            *(__half2*)(g_h1h + (size_t)(r + 8) * F_ + col) =
                __floats2half2_rn(fmaxf(c[mi][ni][2] + bi0, 0.f),
                                  fmaxf(c[mi][ni][3] + bi1, 0.f));
        }
    }
}

// ------------------- GEMM2: out[t] = x[t] + alpha*(h1 @ w2[e]^T + b2[e]) -------------------
// grid: (D/128, MAX_TILES), 256 threads
__global__ __launch_bounds__(256, 2) void gemm2_kernel(const float* __restrict__ x,
                                                       const float* __restrict__ b2,
                                                       float* __restrict__ out) {
    int ti = blockIdx.y;
    if (ti >= g_numTiles) return;
    int e = g_tileE[ti], row0 = g_tileRow[ti], rend = g_tileEnd[ti];
    int n0 = blockIdx.x * 128;

    __shared__ __align__(16) __half As[2][128][40];
    __shared__ __align__(16) __half Bs[2][128][40];

    const __half* Ag = g_h1h + (size_t)row0 * F_;
    const __half* Bg = g_w2h + (size_t)e * D_ * F_ + (size_t)n0 * F_;

    int tid = threadIdx.x;
    int warp = tid >> 5, lane = tid & 31;
    int g = lane >> 2, tg = lane & 3;
    int wm = warp >> 1, wn = warp & 1;

    float c[2][8][4];
#pragma unroll
    for (int mi = 0; mi < 2; mi++)
#pragma unroll
        for (int ni = 0; ni < 8; ni++)
#pragma unroll
            for (int k = 0; k < 4; k++) c[mi][ni][k] = 0.f;

    constexpr int STEPS = F_ / 32;
    issue_tile<F_>(Ag, Bg, 0, 128, As[0], Bs[0], tid);
#pragma unroll 1
    for (int i = 0; i < STEPS; i++) {
        if (i + 1 < STEPS) {
            issue_tile<F_>(Ag, Bg, (i + 1) * 32, 128, As[(i + 1) & 1], Bs[(i + 1) & 1], tid);
            cp_wait<1>();
        } else {
            cp_wait<0>();
        }
        __syncthreads();
        compute_stage(As[i & 1], Bs[i & 1], c, wm, wn, g, tg);
        __syncthreads();
    }

    // epilogue: residual + alpha scale, guarded by real row count
#pragma unroll
    for (int ni = 0; ni < 8; ni++) {
        int col = n0 + wn * 64 + ni * 8 + 2 * tg;
        float bi0 = b2[(size_t)e * D_ + col];
        float bi1 = b2[(size_t)e * D_ + col + 1];
#pragma unroll
        for (int mi = 0; mi < 2; mi++) {
            int r = row0 + wm * 32 + mi * 16 + g;
            if (r < rend) {
                int t = g_srt[r];
                float al = g_alpha[t];
                float2 xv = *(const float2*)(x + (size_t)t * D_ + col);
                float2 o;
                o.x = xv.x + al * (c[mi][ni][0] + bi0);
                o.y = xv.y + al * (c[mi][ni][1] + bi1);
                *(float2*)(out + (size_t)t * D_ + col) = o;
            }
            if (r + 8 < rend) {
                int t = g_srt[r + 8];
                float al = g_alpha[t];
                float2 xv = *(const float2*)(x + (size_t)t * D_ + col);
                float2 o;
                o.x = xv.x + al * (c[mi][ni][2] + bi0);
                o.y = xv.y + al * (c[mi][ni][3] + bi1);
                *(float2*)(out + (size_t)t * D_ + col) = o;
            }
        }
    }
}

// ------------------- launch -------------------
extern "C" void kernel_launch(void* const* d_in, const int* in_sizes, int n_in,
                              void* d_out, int out_size) {
    const float* x    = (const float*)d_in[0];
    const float* cent = (const float*)d_in[1];
    const float* lng  = (const float*)d_in[2];
    const float* lnb  = (const float*)d_in[3];
    const float* w1   = (const float*)d_in[4];
    const float* b1   = (const float*)d_in[5];
    const float* w2   = (const float*)d_in[6];
    const float* b2   = (const float*)d_in[7];
    float* out = (float*)d_out;

    init_kernel<<<1, 32>>>();
    convert_kernel<<<4096, 256>>>(w1, 0);
    convert_kernel<<<4096, 256>>>(w2, 1);
    routing_kernel<<<T_ / 8, 256>>>(x, cent);
    scan_kernel<<<1, 1>>>();
    scatter_kernel<<<T_ / 256, 256>>>();
    ln_kernel<<<T_, 256>>>(x, lng, lnb);
    gemm1_kernel<<<dim3(F_ / 128, MAX_TILES), 256>>>(b1);
    gemm2_kernel<<<dim3(D_ / 128, MAX_TILES), 256>>>(x, b2, out);
}

// round 5
// speedup vs baseline: 1.7759x; 1.6505x over previous
#include <cuda_runtime.h>
#include <cuda_fp16.h>
#include <cstdint>

#define E_ 8
#define D_ 1024
#define F_ 4096
#define T_ 8192
#define TPAD (T_ + E_ * 128)     // 9216: per-expert 128-alignment padding
#define MAX_TILES 80

#define STAGES 4
#define STAGE_BYTES 32768        // A 16KB + B 16KB (128 rows x 64 halves each)
#define SMEM_TOTAL (STAGES * STAGE_BYTES)   // 131072

// ------------------- scratch (device globals; no runtime allocs) -------------------
__device__ __half g_w1h[(size_t)E_ * F_ * D_];
__device__ __half g_w2h[(size_t)E_ * D_ * F_];
__device__ __half g_hnh[(size_t)TPAD * D_];
__device__ __half g_h1h[(size_t)TPAD * F_];
__device__ float  g_alpha[T_];
__device__ int    g_assign[T_];
__device__ int    g_srt[TPAD];
__device__ int    g_pos[T_];
__device__ int    g_counts[E_];
__device__ int    g_offsets[E_];
__device__ int    g_cursor[E_];
__device__ int    g_tileE[MAX_TILES];
__device__ int    g_tileRow[MAX_TILES];
__device__ int    g_tileEnd[MAX_TILES];
__device__ int    g_numTiles;

// ------------------- ptx helpers -------------------
__device__ __forceinline__ uint32_t smem_u32(const void* p) {
    return (uint32_t)__cvta_generic_to_shared(p);
}
__device__ __forceinline__ void cp16(uint32_t dst, const void* src, bool pred) {
    asm volatile("cp.async.cg.shared.global [%0], [%1], 16, %2;\n"
                 :: "r"(dst), "l"(src), "r"(pred ? 16 : 0));
}
__device__ __forceinline__ void cp_commit() { asm volatile("cp.async.commit_group;\n"); }
template <int N>
__device__ __forceinline__ void cp_wait() { asm volatile("cp.async.wait_group %0;\n" :: "n"(N)); }

__device__ __forceinline__ void ldsm_x4(uint32_t r[4], uint32_t addr) {
    asm volatile("ldmatrix.sync.aligned.m8n8.x4.shared.b16 {%0,%1,%2,%3}, [%4];"
                 : "=r"(r[0]), "=r"(r[1]), "=r"(r[2]), "=r"(r[3]) : "r"(addr));
}

__device__ __forceinline__ void mma_16x8x16(float c[4], const uint32_t a[4], const uint32_t b[2]) {
    asm volatile(
        "mma.sync.aligned.m16n8k16.row.col.f32.f16.f16.f32 "
        "{%0,%1,%2,%3}, {%4,%5,%6,%7}, {%8,%9}, {%0,%1,%2,%3};"
        : "+f"(c[0]), "+f"(c[1]), "+f"(c[2]), "+f"(c[3])
        : "r"(a[0]), "r"(a[1]), "r"(a[2]), "r"(a[3]), "r"(b[0]), "r"(b[1]));
}

// ------------------- init -------------------
__global__ void init_kernel() {
    int i = threadIdx.x;
    if (i < E_) g_counts[i] = 0;
}

// ------------------- fp32 -> fp16 weight conversion -------------------
__global__ void convert_kernel(const float* __restrict__ src, int which) {
    __half* dst = which ? g_w2h : g_w1h;
    size_t n4 = ((size_t)E_ * F_ * D_) / 4;
    size_t stride = (size_t)gridDim.x * blockDim.x;
    for (size_t i = (size_t)blockIdx.x * blockDim.x + threadIdx.x; i < n4; i += stride) {
        float4 v = ((const float4*)src)[i];
        ((__half2*)dst)[2 * i]     = __floats2half2_rn(v.x, v.y);
        ((__half2*)dst)[2 * i + 1] = __floats2half2_rn(v.z, v.w);
    }
}

// ------------------- routing -------------------
__global__ void routing_kernel(const float* __restrict__ x, const float* __restrict__ cent) {
    __shared__ float4 sc[E_][D_ / 4];
    int tid = threadIdx.x;
    for (int i = tid; i < E_ * D_ / 4; i += 256)
        ((float4*)&sc[0][0])[i] = ((const float4*)cent)[i];
    __syncthreads();

    int warp = tid >> 5, lane = tid & 31;
    int t = blockIdx.x * 8 + warp;
    const float4* xv = (const float4*)(x + (size_t)t * D_);

    float acc[E_];
#pragma unroll
    for (int e = 0; e < E_; e++) acc[e] = 0.f;
#pragma unroll
    for (int j = 0; j < 8; j++) {
        float4 v = xv[j * 32 + lane];
#pragma unroll
        for (int e = 0; e < E_; e++) {
            float4 c = sc[e][j * 32 + lane];
            acc[e] += v.x * c.x + v.y * c.y + v.z * c.z + v.w * c.w;
        }
    }
#pragma unroll
    for (int e = 0; e < E_; e++) {
#pragma unroll
        for (int off = 16; off > 0; off >>= 1)
            acc[e] += __shfl_xor_sync(0xFFFFFFFFu, acc[e], off);
    }
    if (lane == 0) {
        int best = 0; float bv = acc[0];
#pragma unroll
        for (int e = 1; e < E_; e++)
            if (acc[e] > bv) { bv = acc[e]; best = e; }
        g_assign[t] = best;
        g_alpha[t] = 1.f / (1.f + expf(-bv));
        atomicAdd(&g_counts[best], 1);
    }
}

// ------------------- scan -------------------
__global__ void scan_kernel() {
    if (threadIdx.x != 0) return;
    int off = 0, nt = 0;
    for (int e = 0; e < E_; e++) {
        g_offsets[e] = off;
        g_cursor[e] = off;
        int s1 = off + g_counts[e];
        for (int r = off; r < s1; r += 128) {
            g_tileE[nt]   = e;
            g_tileRow[nt] = r;
            g_tileEnd[nt] = s1;
            nt++;
        }
        off = (s1 + 127) & ~127;
    }
    g_numTiles = nt;
}

// ------------------- scatter -------------------
__global__ void scatter_kernel() {
    int t = blockIdx.x * blockDim.x + threadIdx.x;
    if (t >= T_) return;
    int e = g_assign[t];
    int s = atomicAdd(&g_cursor[e], 1);
    g_srt[s] = t;
    g_pos[t] = s;
}

// ------------------- layernorm -> fp16 sorted -------------------
__global__ void ln_kernel(const float* __restrict__ x,
                          const float* __restrict__ lng,
                          const float* __restrict__ lnb) {
    int t = blockIdx.x;
    int s = g_pos[t];
    int e = g_assign[t];
    int tid = threadIdx.x;

    float4 v = ((const float4*)(x + (size_t)t * D_))[tid];
    float sum = v.x + v.y + v.z + v.w;
    float sq  = v.x * v.x + v.y * v.y + v.z * v.z + v.w * v.w;

    __shared__ float red[2][8];
    int warp = tid >> 5, lane = tid & 31;
#pragma unroll
    for (int off = 16; off > 0; off >>= 1) {
        sum += __shfl_xor_sync(0xFFFFFFFFu, sum, off);
        sq  += __shfl_xor_sync(0xFFFFFFFFu, sq,  off);
    }
    if (lane == 0) { red[0][warp] = sum; red[1][warp] = sq; }
    __syncthreads();
    float tot = 0.f, totsq = 0.f;
#pragma unroll
    for (int w = 0; w < 8; w++) { tot += red[0][w]; totsq += red[1][w]; }
    float mu = tot * (1.f / D_);
    float var = totsq * (1.f / D_) - mu * mu;
    float rstd = rsqrtf(var + 1e-5f);

    float4 gg = ((const float4*)(lng + (size_t)e * D_))[tid];
    float4 bb = ((const float4*)(lnb + (size_t)e * D_))[tid];
    __half2 h0 = __floats2half2_rn((v.x - mu) * rstd * gg.x + bb.x,
                                   (v.y - mu) * rstd * gg.y + bb.y);
    __half2 h1 = __floats2half2_rn((v.z - mu) * rstd * gg.z + bb.z,
                                   (v.w - mu) * rstd * gg.w + bb.w);
    __half2* dst = (__half2*)(g_hnh + (size_t)s * D_);
    dst[2 * tid]     = h0;
    dst[2 * tid + 1] = h1;
}

// ===================================================================
// mma.sync GEMM with ldmatrix + 4-stage cp.async.
// Tile M=128 x N=128, K-stage 64.  8 warps: wm = warp>>1 (M32), wn = warp&1 (N64).
// SW128 swizzle: addr = row*128 + ((lowbytes) ^ ((row&7)<<4)).
// SECOND=false: h1 = relu(hn @ w1[e]^T + b1)   (fp16 out, sorted-padded)
// SECOND=true : out[t] = x[t] + alpha*(h1 @ w2[e]^T + b2)
// ===================================================================

template<int KDIM>
__device__ __forceinline__ void issue_stage(const __half* __restrict__ Ag,
                                            const __half* __restrict__ Bg,
                                            int k0, int rendRel,
                                            uint32_t aBase, uint32_t bBase, int tid) {
#pragma unroll
    for (int i = 0; i < 4; i++) {           // A: 1024 cp16 (128 rows x 8 chunks)
        int idx = tid + i * 256;
        int row = idx >> 3, ch = idx & 7;
        uint32_t so = (uint32_t)row * 128 + (uint32_t)((ch ^ (row & 7)) << 4);
        cp16(aBase + so, Ag + (size_t)row * KDIM + k0 + ch * 8, row < rendRel);
    }
#pragma unroll
    for (int i = 0; i < 4; i++) {           // B: 1024 cp16
        int idx = tid + i * 256;
        int row = idx >> 3, ch = idx & 7;
        uint32_t so = (uint32_t)row * 128 + (uint32_t)((ch ^ (row & 7)) << 4);
        cp16(bBase + so, Bg + (size_t)row * KDIM + k0 + ch * 8, true);
    }
}

__device__ __forceinline__ void compute_stage64(uint32_t aB, uint32_t bB,
                                                float c[2][8][4],
                                                int wm, int wn, int lrow) {
    // lrow = lane & 15 (matrix row), khalf = lane>>4 selects k byte-half
    int khalf16 = ((lrow >> 31) & 0) /*dummy*/;
    (void)khalf16;
#pragma unroll
    for (int kk = 0; kk < 4; kk++) {
        uint32_t a0[4], a1[4];
        {
            int r = wm * 32 + lrow;
            uint32_t low = 0; // filled below per-lane
            (void)low;
        }
        // recompute per call: lane khalf
        int lane = threadIdx.x & 31;
        int khalf = lane >> 4;
        uint32_t low = (uint32_t)(khalf * 16 + kk * 32);
        {
            int r = wm * 32 + (lane & 15);
            ldsm_x4(a0, aB + (uint32_t)r * 128 + (low ^ (uint32_t)((r & 7) << 4)));
        }
        {
            int r = wm * 32 + 16 + (lane & 15);
            ldsm_x4(a1, aB + (uint32_t)r * 128 + (low ^ (uint32_t)((r & 7) << 4)));
        }
#pragma unroll
        for (int ni2 = 0; ni2 < 4; ni2++) {
            uint32_t q[4];
            int r = wn * 64 + ni2 * 16 + (lane & 15);
            ldsm_x4(q, bB + (uint32_t)r * 128 + (low ^ (uint32_t)((r & 7) << 4)));
            uint32_t b0[2] = {q[0], q[2]};
            uint32_t b1[2] = {q[1], q[3]};
            mma_16x8x16(c[0][2 * ni2],     a0, b0);
            mma_16x8x16(c[1][2 * ni2],     a1, b0);
            mma_16x8x16(c[0][2 * ni2 + 1], a0, b1);
            mma_16x8x16(c[1][2 * ni2 + 1], a1, b1);
        }
    }
}

template<int KDIM, bool SECOND>
__global__ __launch_bounds__(256, 1) void hgemm(const float* __restrict__ bias,
                                                const float* __restrict__ x,
                                                float* __restrict__ out) {
    int ti = blockIdx.y;
    if (ti >= g_numTiles) return;
    int e = g_tileE[ti], row0 = g_tileRow[ti], rend = g_tileEnd[ti];
    int n0 = blockIdx.x * 128;
    int rendRel = rend - row0;
    constexpr int NOUT = SECOND ? D_ : F_;

    const __half* Ag = (SECOND ? g_h1h : g_hnh) + (size_t)row0 * KDIM;
    const __half* Bg = (SECOND ? g_w2h : g_w1h) + (size_t)e * ((size_t)F_ * D_) + (size_t)n0 * KDIM;
    const float*  brow = bias + (size_t)e * NOUT + n0;

    extern __shared__ __align__(1024) uint8_t smem[];
    uint32_t sb = smem_u32(smem);

    int tid = threadIdx.x, warp = tid >> 5, lane = tid & 31;
    int wm = warp >> 1, wn = warp & 1;
    int g = lane >> 2, tg = lane & 3;
    int lrow = lane & 15;

    float c[2][8][4];
#pragma unroll
    for (int mi = 0; mi < 2; mi++)
#pragma unroll
        for (int ni = 0; ni < 8; ni++)
#pragma unroll
            for (int k = 0; k < 4; k++) c[mi][ni][k] = 0.f;

    constexpr int CH = KDIM / 64;

    // prologue: stages 0..2
#pragma unroll
    for (int s = 0; s < 3; s++) {
        issue_stage<KDIM>(Ag, Bg, s * 64, rendRel,
                          sb + s * STAGE_BYTES, sb + s * STAGE_BYTES + 16384, tid);
        cp_commit();
    }

#pragma unroll 1
    for (int i = 0; i < CH; i++) {
        cp_wait<2>();
        __syncthreads();
        if (i + 3 < CH) {
            int s = (i + 3) & (STAGES - 1);
            issue_stage<KDIM>(Ag, Bg, (i + 3) * 64, rendRel,
                              sb + s * STAGE_BYTES, sb + s * STAGE_BYTES + 16384, tid);
        }
        cp_commit();   // uniform commit (empty near the tail) keeps wait<2> aligned
        int s = i & (STAGES - 1);
        compute_stage64(sb + s * STAGE_BYTES, sb + s * STAGE_BYTES + 16384, c, wm, wn, lrow);
        __syncthreads();
    }

    // ---------------- epilogue ----------------
    if (!SECOND) {
#pragma unroll
        for (int ni = 0; ni < 8; ni++) {
            int col = n0 + wn * 64 + ni * 8 + 2 * tg;
            float bi0 = __ldg(&brow[wn * 64 + ni * 8 + 2 * tg]);
            float bi1 = __ldg(&brow[wn * 64 + ni * 8 + 2 * tg + 1]);
#pragma unroll
            for (int mi = 0; mi < 2; mi++) {
                int r = row0 + wm * 32 + mi * 16 + g;
                *(__half2*)(g_h1h + (size_t)r * F_ + col) =
                    __floats2half2_rn(fmaxf(c[mi][ni][0] + bi0, 0.f),
                                      fmaxf(c[mi][ni][1] + bi1, 0.f));
                *(__half2*)(g_h1h + (size_t)(r + 8) * F_ + col) =
                    __floats2half2_rn(fmaxf(c[mi][ni][2] + bi0, 0.f),
                                      fmaxf(c[mi][ni][3] + bi1, 0.f));
            }
        }
    } else {
#pragma unroll
        for (int ni = 0; ni < 8; ni++) {
            int col = n0 + wn * 64 + ni * 8 + 2 * tg;
            float bi0 = __ldg(&brow[wn * 64 + ni * 8 + 2 * tg]);
            float bi1 = __ldg(&brow[wn * 64 + ni * 8 + 2 * tg + 1]);
#pragma unroll
            for (int mi = 0; mi < 2; mi++) {
                int r = row0 + wm * 32 + mi * 16 + g;
                if (r < rend) {
                    int t = g_srt[r];
                    float al = g_alpha[t];
                    float2 xv = *(const float2*)(x + (size_t)t * D_ + col);
                    float2 o;
                    o.x = xv.x + al * (c[mi][ni][0] + bi0);
                    o.y = xv.y + al * (c[mi][ni][1] + bi1);
                    *(float2*)(out + (size_t)t * D_ + col) = o;
                }
                if (r + 8 < rend) {
                    int t = g_srt[r + 8];
                    float al = g_alpha[t];
                    float2 xv = *(const float2*)(x + (size_t)t * D_ + col);
                    float2 o;
                    o.x = xv.x + al * (c[mi][ni][2] + bi0);
                    o.y = xv.y + al * (c[mi][ni][3] + bi1);
                    *(float2*)(out + (size_t)t * D_ + col) = o;
                }
            }
        }
    }
}

// ------------------- launch -------------------
extern "C" void kernel_launch(void* const* d_in, const int* in_sizes, int n_in,
                              void* d_out, int out_size) {
    const float* x    = (const float*)d_in[0];
    const float* cent = (const float*)d_in[1];
    const float* lng  = (const float*)d_in[2];
    const float* lnb  = (const float*)d_in[3];
    const float* w1   = (const float*)d_in[4];
    const float* b1   = (const float*)d_in[5];
    const float* w2   = (const float*)d_in[6];
    const float* b2   = (const float*)d_in[7];
    float* out = (float*)d_out;

    cudaFuncSetAttribute(hgemm<D_, false>, cudaFuncAttributeMaxDynamicSharedMemorySize, SMEM_TOTAL);
    cudaFuncSetAttribute(hgemm<F_, true>,  cudaFuncAttributeMaxDynamicSharedMemorySize, SMEM_TOTAL);

    init_kernel<<<1, 32>>>();
    convert_kernel<<<4096, 256>>>(w1, 0);
    convert_kernel<<<4096, 256>>>(w2, 1);
    routing_kernel<<<T_ / 8, 256>>>(x, cent);
    scan_kernel<<<1, 1>>>();
    scatter_kernel<<<T_ / 256, 256>>>();
    ln_kernel<<<T_, 256>>>(x, lng, lnb);
    hgemm<D_, false><<<dim3(F_ / 128, MAX_TILES), 256, SMEM_TOTAL>>>(b1, nullptr, nullptr);
    hgemm<F_, true><<<dim3(D_ / 128, MAX_TILES), 256, SMEM_TOTAL>>>(b2, x, out);
}

// round 6
// speedup vs baseline: 1.8083x; 1.0182x over previous
#include <cuda_runtime.h>
#include <cuda_fp16.h>
#include <cstdint>

#define E_ 8
#define D_ 1024
#define F_ 4096
#define T_ 8192
#define TPAD (T_ + E_ * 128)     // 9216: per-expert 128-alignment padding
#define MAX_TILES 80

#define STAGES 4
#define STAGE_BYTES 49152        // A 16KB (128x64h) + B 32KB (256x64h)
#define SMEM_TOTAL (STAGES * STAGE_BYTES)   // 196608

// ------------------- scratch (device globals; no runtime allocs) -------------------
__device__ __half g_w1h[(size_t)E_ * F_ * D_];
__device__ __half g_w2h[(size_t)E_ * D_ * F_];
__device__ __half g_hnh[(size_t)TPAD * D_];
__device__ __half g_h1h[(size_t)TPAD * F_];
__device__ float  g_alpha[T_];
__device__ int    g_assign[T_];
__device__ int    g_srt[TPAD];
__device__ int    g_pos[T_];
__device__ int    g_counts[E_];
__device__ int    g_offsets[E_];
__device__ int    g_cursor[E_];
__device__ int    g_tileE[MAX_TILES];
__device__ int    g_tileRow[MAX_TILES];
__device__ int    g_tileEnd[MAX_TILES];
__device__ int    g_numTiles;

// ------------------- ptx helpers -------------------
__device__ __forceinline__ uint32_t smem_u32(const void* p) {
    return (uint32_t)__cvta_generic_to_shared(p);
}
__device__ __forceinline__ void cp16(uint32_t dst, const void* src, bool pred) {
    asm volatile("cp.async.cg.shared.global [%0], [%1], 16, %2;\n"
                 :: "r"(dst), "l"(src), "r"(pred ? 16 : 0));
}
__device__ __forceinline__ void cp_commit() { asm volatile("cp.async.commit_group;\n"); }
template <int N>
__device__ __forceinline__ void cp_wait() { asm volatile("cp.async.wait_group %0;\n" :: "n"(N)); }

__device__ __forceinline__ void ldsm_x4(uint32_t r[4], uint32_t addr) {
    asm volatile("ldmatrix.sync.aligned.m8n8.x4.shared.b16 {%0,%1,%2,%3}, [%4];"
                 : "=r"(r[0]), "=r"(r[1]), "=r"(r[2]), "=r"(r[3]) : "r"(addr));
}

__device__ __forceinline__ void mma_16x8x16(float c[4], const uint32_t a[4], const uint32_t b[2]) {
    asm volatile(
        "mma.sync.aligned.m16n8k16.row.col.f32.f16.f16.f32 "
        "{%0,%1,%2,%3}, {%4,%5,%6,%7}, {%8,%9}, {%0,%1,%2,%3};"
        : "+f"(c[0]), "+f"(c[1]), "+f"(c[2]), "+f"(c[3])
        : "r"(a[0]), "r"(a[1]), "r"(a[2]), "r"(a[3]), "r"(b[0]), "r"(b[1]));
}

// ------------------- init -------------------
__global__ void init_kernel() {
    int i = threadIdx.x;
    if (i < E_) g_counts[i] = 0;
}

// ------------------- fp32 -> fp16 weight conversion -------------------
__global__ void convert_kernel(const float* __restrict__ src, int which) {
    __half* dst = which ? g_w2h : g_w1h;
    size_t n4 = ((size_t)E_ * F_ * D_) / 4;
    size_t stride = (size_t)gridDim.x * blockDim.x;
    for (size_t i = (size_t)blockIdx.x * blockDim.x + threadIdx.x; i < n4; i += stride) {
        float4 v = ((const float4*)src)[i];
        ((__half2*)dst)[2 * i]     = __floats2half2_rn(v.x, v.y);
        ((__half2*)dst)[2 * i + 1] = __floats2half2_rn(v.z, v.w);
    }
}

// ------------------- routing -------------------
__global__ void routing_kernel(const float* __restrict__ x, const float* __restrict__ cent) {
    __shared__ float4 sc[E_][D_ / 4];
    int tid = threadIdx.x;
    for (int i = tid; i < E_ * D_ / 4; i += 256)
        ((float4*)&sc[0][0])[i] = ((const float4*)cent)[i];
    __syncthreads();

    int warp = tid >> 5, lane = tid & 31;
    int t = blockIdx.x * 8 + warp;
    const float4* xv = (const float4*)(x + (size_t)t * D_);

    float acc[E_];
#pragma unroll
    for (int e = 0; e < E_; e++) acc[e] = 0.f;
#pragma unroll
    for (int j = 0; j < 8; j++) {
        float4 v = xv[j * 32 + lane];
#pragma unroll
        for (int e = 0; e < E_; e++) {
            float4 c = sc[e][j * 32 + lane];
            acc[e] += v.x * c.x + v.y * c.y + v.z * c.z + v.w * c.w;
        }
    }
#pragma unroll
    for (int e = 0; e < E_; e++) {
#pragma unroll
        for (int off = 16; off > 0; off >>= 1)
            acc[e] += __shfl_xor_sync(0xFFFFFFFFu, acc[e], off);
    }
    if (lane == 0) {
        int best = 0; float bv = acc[0];
#pragma unroll
        for (int e = 1; e < E_; e++)
            if (acc[e] > bv) { bv = acc[e]; best = e; }
        g_assign[t] = best;
        g_alpha[t] = 1.f / (1.f + expf(-bv));
        atomicAdd(&g_counts[best], 1);
    }
}

// ------------------- scan -------------------
__global__ void scan_kernel() {
    if (threadIdx.x != 0) return;
    int off = 0, nt = 0;
    for (int e = 0; e < E_; e++) {
        g_offsets[e] = off;
        g_cursor[e] = off;
        int s1 = off + g_counts[e];
        for (int r = off; r < s1; r += 128) {
            g_tileE[nt]   = e;
            g_tileRow[nt] = r;
            g_tileEnd[nt] = s1;
            nt++;
        }
        off = (s1 + 127) & ~127;
    }
    g_numTiles = nt;
}

// ------------------- scatter -------------------
__global__ void scatter_kernel() {
    int t = blockIdx.x * blockDim.x + threadIdx.x;
    if (t >= T_) return;
    int e = g_assign[t];
    int s = atomicAdd(&g_cursor[e], 1);
    g_srt[s] = t;
    g_pos[t] = s;
}

// ------------------- layernorm -> fp16 sorted -------------------
__global__ void ln_kernel(const float* __restrict__ x,
                          const float* __restrict__ lng,
                          const float* __restrict__ lnb) {
    int t = blockIdx.x;
    int s = g_pos[t];
    int e = g_assign[t];
    int tid = threadIdx.x;

    float4 v = ((const float4*)(x + (size_t)t * D_))[tid];
    float sum = v.x + v.y + v.z + v.w;
    float sq  = v.x * v.x + v.y * v.y + v.z * v.z + v.w * v.w;

    __shared__ float red[2][8];
    int warp = tid >> 5, lane = tid & 31;
#pragma unroll
    for (int off = 16; off > 0; off >>= 1) {
        sum += __shfl_xor_sync(0xFFFFFFFFu, sum, off);
        sq  += __shfl_xor_sync(0xFFFFFFFFu, sq,  off);
    }
    if (lane == 0) { red[0][warp] = sum; red[1][warp] = sq; }
    __syncthreads();
    float tot = 0.f, totsq = 0.f;
#pragma unroll
    for (int w = 0; w < 8; w++) { tot += red[0][w]; totsq += red[1][w]; }
    float mu = tot * (1.f / D_);
    float var = totsq * (1.f / D_) - mu * mu;
    float rstd = rsqrtf(var + 1e-5f);

    float4 gg = ((const float4*)(lng + (size_t)e * D_))[tid];
    float4 bb = ((const float4*)(lnb + (size_t)e * D_))[tid];
    __half2 h0 = __floats2half2_rn((v.x - mu) * rstd * gg.x + bb.x,
                                   (v.y - mu) * rstd * gg.y + bb.y);
    __half2 h1 = __floats2half2_rn((v.z - mu) * rstd * gg.z + bb.z,
                                   (v.w - mu) * rstd * gg.w + bb.w);
    __half2* dst = (__half2*)(g_hnh + (size_t)s * D_);
    dst[2 * tid]     = h0;
    dst[2 * tid + 1] = h1;
}

// ===================================================================
// mma.sync GEMM: CTA tile M=128 x N=256, K-stage 64, 4-stage cp.async.
// 8 warps as 2(m) x 4(n); warp tile 64x64.
// Per K16 slice per warp: 8 ldmatrix.x4 + 32 HMMA.
// SECOND=false: h1 = relu(hn @ w1[e]^T + b1)   (fp16 out, sorted-padded)
// SECOND=true : out[t] = x[t] + alpha*(h1 @ w2[e]^T + b2)
// ===================================================================

template<int KDIM>
__device__ __forceinline__ void issue_stage(const __half* __restrict__ Ag,
                                            const __half* __restrict__ Bg,
                                            int k0, int rendRel,
                                            uint32_t aBase, uint32_t bBase, int tid) {
#pragma unroll
    for (int i = 0; i < 4; i++) {           // A: 1024 cp16 (128 rows x 8 chunks)
        int idx = tid + i * 256;
        int row = idx >> 3, ch = idx & 7;
        uint32_t so = (uint32_t)row * 128 + (uint32_t)((ch ^ (row & 7)) << 4);
        cp16(aBase + so, Ag + (size_t)row * KDIM + k0 + ch * 8, row < rendRel);
    }
#pragma unroll
    for (int i = 0; i < 8; i++) {           // B: 2048 cp16 (256 rows x 8 chunks)
        int idx = tid + i * 256;
        int row = idx >> 3, ch = idx & 7;
        uint32_t so = (uint32_t)row * 128 + (uint32_t)((ch ^ (row & 7)) << 4);
        cp16(bBase + so, Bg + (size_t)row * KDIM + k0 + ch * 8, true);
    }
}

__device__ __forceinline__ void compute_stage64(uint32_t aB, uint32_t bB,
                                                float c[4][8][4],
                                                int wm, int wn) {
    int lane = threadIdx.x & 31;
    int lr = lane & 15;
    uint32_t khoff = (uint32_t)((lane >> 4) * 16);
#pragma unroll
    for (int kk = 0; kk < 4; kk++) {
        uint32_t low = khoff + (uint32_t)(kk * 32);
        uint32_t a[4][4];
#pragma unroll
        for (int mi = 0; mi < 4; mi++) {
            int r = wm * 64 + mi * 16 + lr;
            ldsm_x4(a[mi], aB + (uint32_t)r * 128 + (low ^ (uint32_t)((r & 7) << 4)));
        }
#pragma unroll
        for (int ni2 = 0; ni2 < 4; ni2++) {
            uint32_t q[4];
            int r = wn * 64 + ni2 * 16 + lr;
            ldsm_x4(q, bB + (uint32_t)r * 128 + (low ^ (uint32_t)((r & 7) << 4)));
            uint32_t b0[2] = {q[0], q[2]};
            uint32_t b1[2] = {q[1], q[3]};
#pragma unroll
            for (int mi = 0; mi < 4; mi++) {
                mma_16x8x16(c[mi][2 * ni2],     a[mi], b0);
                mma_16x8x16(c[mi][2 * ni2 + 1], a[mi], b1);
            }
        }
    }
}

template<int KDIM, bool SECOND>
__global__ __launch_bounds__(256, 1) void hgemm(const float* __restrict__ bias,
                                                const float* __restrict__ x,
                                                float* __restrict__ out) {
    int ti = blockIdx.y;
    if (ti >= g_numTiles) return;
    int e = g_tileE[ti], row0 = g_tileRow[ti], rend = g_tileEnd[ti];
    int n0 = blockIdx.x * 256;
    int rendRel = rend - row0;
    constexpr int NOUT = SECOND ? D_ : F_;

    const __half* Ag = (SECOND ? g_h1h : g_hnh) + (size_t)row0 * KDIM;
    const __half* Bg = (SECOND ? g_w2h : g_w1h) + (size_t)e * ((size_t)F_ * D_) + (size_t)n0 * KDIM;
    const float*  brow = bias + (size_t)e * NOUT + n0;

    extern __shared__ __align__(1024) uint8_t smem[];
    uint32_t sb = smem_u32(smem);

    int tid = threadIdx.x, warp = tid >> 5, lane = tid & 31;
    int wm = warp >> 2, wn = warp & 3;
    int g = lane >> 2, tg = lane & 3;

    float c[4][8][4];
#pragma unroll
    for (int mi = 0; mi < 4; mi++)
#pragma unroll
        for (int ni = 0; ni < 8; ni++)
#pragma unroll
            for (int k = 0; k < 4; k++) c[mi][ni][k] = 0.f;

    constexpr int CH = KDIM / 64;

    // prologue: stages 0..2
#pragma unroll
    for (int s = 0; s < 3; s++) {
        issue_stage<KDIM>(Ag, Bg, s * 64, rendRel,
                          sb + s * STAGE_BYTES, sb + s * STAGE_BYTES + 16384, tid);
        cp_commit();
    }

#pragma unroll 1
    for (int i = 0; i < CH; i++) {
        cp_wait<2>();
        __syncthreads();
        if (i + 3 < CH) {
            int s = (i + 3) & (STAGES - 1);
            issue_stage<KDIM>(Ag, Bg, (i + 3) * 64, rendRel,
                              sb + s * STAGE_BYTES, sb + s * STAGE_BYTES + 16384, tid);
        }
        cp_commit();   // uniform commit keeps wait<2> aligned near the tail
        int s = i & (STAGES - 1);
        compute_stage64(sb + s * STAGE_BYTES, sb + s * STAGE_BYTES + 16384, c, wm, wn);
        __syncthreads();
    }

    // ---------------- epilogue ----------------
    if (!SECOND) {
#pragma unroll
        for (int ni = 0; ni < 8; ni++) {
            int col = n0 + wn * 64 + ni * 8 + 2 * tg;
            float bi0 = __ldg(&brow[wn * 64 + ni * 8 + 2 * tg]);
            float bi1 = __ldg(&brow[wn * 64 + ni * 8 + 2 * tg + 1]);
#pragma unroll
            for (int mi = 0; mi < 4; mi++) {
                int r = row0 + wm * 64 + mi * 16 + g;
                *(__half2*)(g_h1h + (size_t)r * F_ + col) =
                    __floats2half2_rn(fmaxf(c[mi][ni][0] + bi0, 0.f),
                                      fmaxf(c[mi][ni][1] + bi1, 0.f));
                *(__half2*)(g_h1h + (size_t)(r + 8) * F_ + col) =
                    __floats2half2_rn(fmaxf(c[mi][ni][2] + bi0, 0.f),
                                      fmaxf(c[mi][ni][3] + bi1, 0.f));
            }
        }
    } else {
#pragma unroll
        for (int ni = 0; ni < 8; ni++) {
            int col = n0 + wn * 64 + ni * 8 + 2 * tg;
            float bi0 = __ldg(&brow[wn * 64 + ni * 8 + 2 * tg]);
            float bi1 = __ldg(&brow[wn * 64 + ni * 8 + 2 * tg + 1]);
#pragma unroll
            for (int mi = 0; mi < 4; mi++) {
                int r = row0 + wm * 64 + mi * 16 + g;
                if (r < rend) {
                    int t = g_srt[r];
                    float al = g_alpha[t];
                    float2 xv = *(const float2*)(x + (size_t)t * D_ + col);
                    float2 o;
                    o.x = xv.x + al * (c[mi][ni][0] + bi0);
                    o.y = xv.y + al * (c[mi][ni][1] + bi1);
                    *(float2*)(out + (size_t)t * D_ + col) = o;
                }
                if (r + 8 < rend) {
                    int t = g_srt[r + 8];
                    float al = g_alpha[t];
                    float2 xv = *(const float2*)(x + (size_t)t * D_ + col);
                    float2 o;
                    o.x = xv.x + al * (c[mi][ni][2] + bi0);
                    o.y = xv.y + al * (c[mi][ni][3] + bi1);
                    *(float2*)(out + (size_t)t * D_ + col) = o;
                }
            }
        }
    }
}

// ------------------- launch -------------------
extern "C" void kernel_launch(void* const* d_in, const int* in_sizes, int n_in,
                              void* d_out, int out_size) {
    const float* x    = (const float*)d_in[0];
    const float* cent = (const float*)d_in[1];
    const float* lng  = (const float*)d_in[2];
    const float* lnb  = (const float*)d_in[3];
    const float* w1   = (const float*)d_in[4];
    const float* b1   = (const float*)d_in[5];
    const float* w2   = (const float*)d_in[6];
    const float* b2   = (const float*)d_in[7];
    float* out = (float*)d_out;

    cudaFuncSetAttribute(hgemm<D_, false>, cudaFuncAttributeMaxDynamicSharedMemorySize, SMEM_TOTAL);
    cudaFuncSetAttribute(hgemm<F_, true>,  cudaFuncAttributeMaxDynamicSharedMemorySize, SMEM_TOTAL);

    init_kernel<<<1, 32>>>();
    convert_kernel<<<4096, 256>>>(w1, 0);
    convert_kernel<<<4096, 256>>>(w2, 1);
    routing_kernel<<<T_ / 8, 256>>>(x, cent);
    scan_kernel<<<1, 1>>>();
    scatter_kernel<<<T_ / 256, 256>>>();
    ln_kernel<<<T_, 256>>>(x, lng, lnb);
    hgemm<D_, false><<<dim3(F_ / 256, MAX_TILES), 256, SMEM_TOTAL>>>(b1, nullptr, nullptr);
    hgemm<F_, true><<<dim3(D_ / 256, MAX_TILES), 256, SMEM_TOTAL>>>(b2, x, out);
}

// round 7
// speedup vs baseline: 2.0782x; 1.1493x over previous
#include <cuda_runtime.h>
#include <cuda_fp16.h>
#include <cstdint>

#define E_ 8
#define D_ 1024
#define F_ 4096
#define T_ 8192
#define TPAD (T_ + E_ * 128)     // 9216: per-expert 128-alignment padding
#define MAX_TILES 80

#define STAGES 3
#define STAGE_BYTES 32768        // A 16KB (128x64h) + B 16KB (128x64h)
#define SMEM_TOTAL (STAGES * STAGE_BYTES)   // 98304 -> 2 CTAs/SM

// ------------------- scratch (device globals; no runtime allocs) -------------------
__device__ __half g_w1h[(size_t)E_ * F_ * D_];
__device__ __half g_w2h[(size_t)E_ * D_ * F_];
__device__ __half g_hnh[(size_t)TPAD * D_];
__device__ __half g_h1h[(size_t)TPAD * F_];
__device__ float  g_alpha[T_];
__device__ int    g_assign[T_];
__device__ int    g_srt[TPAD];
__device__ int    g_pos[T_];
__device__ int    g_counts[E_];
__device__ int    g_offsets[E_];
__device__ int    g_cursor[E_];
__device__ int    g_tileE[MAX_TILES];
__device__ int    g_tileRow[MAX_TILES];
__device__ int    g_tileEnd[MAX_TILES];
__device__ int    g_numTiles;

// ------------------- ptx helpers -------------------
__device__ __forceinline__ uint32_t smem_u32(const void* p) {
    return (uint32_t)__cvta_generic_to_shared(p);
}
__device__ __forceinline__ void cp16(uint32_t dst, const void* src, bool pred) {
    asm volatile("cp.async.cg.shared.global [%0], [%1], 16, %2;\n"
                 :: "r"(dst), "l"(src), "r"(pred ? 16 : 0));
}
__device__ __forceinline__ void cp_commit() { asm volatile("cp.async.commit_group;\n"); }
template <int N>
__device__ __forceinline__ void cp_wait() { asm volatile("cp.async.wait_group %0;\n" :: "n"(N)); }

__device__ __forceinline__ void ldsm_x4(uint32_t r[4], uint32_t addr) {
    asm volatile("ldmatrix.sync.aligned.m8n8.x4.shared.b16 {%0,%1,%2,%3}, [%4];"
                 : "=r"(r[0]), "=r"(r[1]), "=r"(r[2]), "=r"(r[3]) : "r"(addr));
}

__device__ __forceinline__ void mma_16x8x16(float c[4], const uint32_t a[4], const uint32_t b[2]) {
    asm volatile(
        "mma.sync.aligned.m16n8k16.row.col.f32.f16.f16.f32 "
        "{%0,%1,%2,%3}, {%4,%5,%6,%7}, {%8,%9}, {%0,%1,%2,%3};"
        : "+f"(c[0]), "+f"(c[1]), "+f"(c[2]), "+f"(c[3])
        : "r"(a[0]), "r"(a[1]), "r"(a[2]), "r"(a[3]), "r"(b[0]), "r"(b[1]));
}

// ------------------- init -------------------
__global__ void init_kernel() {
    int i = threadIdx.x;
    if (i < E_) g_counts[i] = 0;
}

// ------------------- fp32 -> fp16 weight conversion -------------------
__global__ void convert_kernel(const float* __restrict__ src, int which) {
    __half* dst = which ? g_w2h : g_w1h;
    size_t n4 = ((size_t)E_ * F_ * D_) / 4;
    size_t stride = (size_t)gridDim.x * blockDim.x;
    for (size_t i = (size_t)blockIdx.x * blockDim.x + threadIdx.x; i < n4; i += stride) {
        float4 v = ((const float4*)src)[i];
        ((__half2*)dst)[2 * i]     = __floats2half2_rn(v.x, v.y);
        ((__half2*)dst)[2 * i + 1] = __floats2half2_rn(v.z, v.w);
    }
}

// ------------------- routing -------------------
__global__ void routing_kernel(const float* __restrict__ x, const float* __restrict__ cent) {
    __shared__ float4 sc[E_][D_ / 4];
    int tid = threadIdx.x;
    for (int i = tid; i < E_ * D_ / 4; i += 256)
        ((float4*)&sc[0][0])[i] = ((const float4*)cent)[i];
    __syncthreads();

    int warp = tid >> 5, lane = tid & 31;
    int t = blockIdx.x * 8 + warp;
    const float4* xv = (const float4*)(x + (size_t)t * D_);

    float acc[E_];
#pragma unroll
    for (int e = 0; e < E_; e++) acc[e] = 0.f;
#pragma unroll
    for (int j = 0; j < 8; j++) {
        float4 v = xv[j * 32 + lane];
#pragma unroll
        for (int e = 0; e < E_; e++) {
            float4 c = sc[e][j * 32 + lane];
            acc[e] += v.x * c.x + v.y * c.y + v.z * c.z + v.w * c.w;
        }
    }
#pragma unroll
    for (int e = 0; e < E_; e++) {
#pragma unroll
        for (int off = 16; off > 0; off >>= 1)
            acc[e] += __shfl_xor_sync(0xFFFFFFFFu, acc[e], off);
    }
    if (lane == 0) {
        int best = 0; float bv = acc[0];
#pragma unroll
        for (int e = 1; e < E_; e++)
            if (acc[e] > bv) { bv = acc[e]; best = e; }
        g_assign[t] = best;
        g_alpha[t] = 1.f / (1.f + expf(-bv));
        atomicAdd(&g_counts[best], 1);
    }
}

// ------------------- scan -------------------
__global__ void scan_kernel() {
    if (threadIdx.x != 0) return;
    int off = 0, nt = 0;
    for (int e = 0; e < E_; e++) {
        g_offsets[e] = off;
        g_cursor[e] = off;
        int s1 = off + g_counts[e];
        for (int r = off; r < s1; r += 128) {
            g_tileE[nt]   = e;
            g_tileRow[nt] = r;
            g_tileEnd[nt] = s1;
            nt++;
        }
        off = (s1 + 127) & ~127;
    }
    g_numTiles = nt;
}

// ------------------- scatter -------------------
__global__ void scatter_kernel() {
    int t = blockIdx.x * blockDim.x + threadIdx.x;
    if (t >= T_) return;
    int e = g_assign[t];
    int s = atomicAdd(&g_cursor[e], 1);
    g_srt[s] = t;
    g_pos[t] = s;
}

// ------------------- layernorm -> fp16 sorted -------------------
__global__ void ln_kernel(const float* __restrict__ x,
                          const float* __restrict__ lng,
                          const float* __restrict__ lnb) {
    int t = blockIdx.x;
    int s = g_pos[t];
    int e = g_assign[t];
    int tid = threadIdx.x;

    float4 v = ((const float4*)(x + (size_t)t * D_))[tid];
    float sum = v.x + v.y + v.z + v.w;
    float sq  = v.x * v.x + v.y * v.y + v.z * v.z + v.w * v.w;

    __shared__ float red[2][8];
    int warp = tid >> 5, lane = tid & 31;
#pragma unroll
    for (int off = 16; off > 0; off >>= 1) {
        sum += __shfl_xor_sync(0xFFFFFFFFu, sum, off);
        sq  += __shfl_xor_sync(0xFFFFFFFFu, sq,  off);
    }
    if (lane == 0) { red[0][warp] = sum; red[1][warp] = sq; }
    __syncthreads();
    float tot = 0.f, totsq = 0.f;
#pragma unroll
    for (int w = 0; w < 8; w++) { tot += red[0][w]; totsq += red[1][w]; }
    float mu = tot * (1.f / D_);
    float var = totsq * (1.f / D_) - mu * mu;
    float rstd = rsqrtf(var + 1e-5f);

    float4 gg = ((const float4*)(lng + (size_t)e * D_))[tid];
    float4 bb = ((const float4*)(lnb + (size_t)e * D_))[tid];
    __half2 h0 = __floats2half2_rn((v.x - mu) * rstd * gg.x + bb.x,
                                   (v.y - mu) * rstd * gg.y + bb.y);
    __half2 h1 = __floats2half2_rn((v.z - mu) * rstd * gg.z + bb.z,
                                   (v.w - mu) * rstd * gg.w + bb.w);
    __half2* dst = (__half2*)(g_hnh + (size_t)s * D_);
    dst[2 * tid]     = h0;
    dst[2 * tid + 1] = h1;
}

// ===================================================================
// mma.sync GEMM: CTA tile M=128 x N=128, K-stage 64, 3-stage cp.async,
// 96KB smem -> 2 CTAs/SM (cross-CTA bubble hiding).
// 8 warps as 4(m) x 2(n); warp tile 32x64.
// SECOND=false: h1 = relu(hn @ w1[e]^T + b1)   (fp16 out, sorted-padded)
// SECOND=true : out[t] = x[t] + alpha*(h1 @ w2[e]^T + b2)
// ===================================================================

template<int KDIM>
__device__ __forceinline__ void issue_stage(const __half* __restrict__ Ag,
                                            const __half* __restrict__ Bg,
                                            int k0, int rendRel,
                                            uint32_t aBase, uint32_t bBase, int tid) {
#pragma unroll
    for (int i = 0; i < 4; i++) {           // A: 1024 cp16 (128 rows x 8 chunks)
        int idx = tid + i * 256;
        int row = idx >> 3, ch = idx & 7;
        uint32_t so = (uint32_t)row * 128 + (uint32_t)((ch ^ (row & 7)) << 4);
        cp16(aBase + so, Ag + (size_t)row * KDIM + k0 + ch * 8, row < rendRel);
    }
#pragma unroll
    for (int i = 0; i < 4; i++) {           // B: 1024 cp16
        int idx = tid + i * 256;
        int row = idx >> 3, ch = idx & 7;
        uint32_t so = (uint32_t)row * 128 + (uint32_t)((ch ^ (row & 7)) << 4);
        cp16(bBase + so, Bg + (size_t)row * KDIM + k0 + ch * 8, true);
    }
}

__device__ __forceinline__ void compute_stage64(uint32_t aB, uint32_t bB,
                                                float c[2][8][4],
                                                int wm, int wn) {
    int lane = threadIdx.x & 31;
    int lr = lane & 15;
    uint32_t khoff = (uint32_t)((lane >> 4) * 16);
#pragma unroll
    for (int kk = 0; kk < 4; kk++) {
        uint32_t low = khoff + (uint32_t)(kk * 32);
        uint32_t a0[4], a1[4];
        {
            int r = wm * 32 + lr;
            ldsm_x4(a0, aB + (uint32_t)r * 128 + (low ^ (uint32_t)((r & 7) << 4)));
        }
        {
            int r = wm * 32 + 16 + lr;
            ldsm_x4(a1, aB + (uint32_t)r * 128 + (low ^ (uint32_t)((r & 7) << 4)));
        }
#pragma unroll
        for (int ni2 = 0; ni2 < 4; ni2++) {
            uint32_t q[4];
            int r = wn * 64 + ni2 * 16 + lr;
            ldsm_x4(q, bB + (uint32_t)r * 128 + (low ^ (uint32_t)((r & 7) << 4)));
            uint32_t b0[2] = {q[0], q[2]};
            uint32_t b1[2] = {q[1], q[3]};
            mma_16x8x16(c[0][2 * ni2],     a0, b0);
            mma_16x8x16(c[1][2 * ni2],     a1, b0);
            mma_16x8x16(c[0][2 * ni2 + 1], a0, b1);
            mma_16x8x16(c[1][2 * ni2 + 1], a1, b1);
        }
    }
}

template<int KDIM, bool SECOND>
__global__ __launch_bounds__(256, 2) void hgemm(const float* __restrict__ bias,
                                                const float* __restrict__ x,
                                                float* __restrict__ out) {
    int ti = blockIdx.y;
    if (ti >= g_numTiles) return;
    int e = g_tileE[ti], row0 = g_tileRow[ti], rend = g_tileEnd[ti];
    int n0 = blockIdx.x * 128;
    int rendRel = rend - row0;
    constexpr int NOUT = SECOND ? D_ : F_;

    const __half* Ag = (SECOND ? g_h1h : g_hnh) + (size_t)row0 * KDIM;
    const __half* Bg = (SECOND ? g_w2h : g_w1h) + (size_t)e * ((size_t)F_ * D_) + (size_t)n0 * KDIM;
    const float*  brow = bias + (size_t)e * NOUT + n0;

    extern __shared__ __align__(1024) uint8_t smem[];
    uint32_t sb = smem_u32(smem);

    int tid = threadIdx.x, warp = tid >> 5, lane = tid & 31;
    int wm = warp >> 1, wn = warp & 1;
    int g = lane >> 2, tg = lane & 3;

    float c[2][8][4];
#pragma unroll
    for (int mi = 0; mi < 2; mi++)
#pragma unroll
        for (int ni = 0; ni < 8; ni++)
#pragma unroll
            for (int k = 0; k < 4; k++) c[mi][ni][k] = 0.f;

    constexpr int CH = KDIM / 64;

    // prologue: stages 0..1
#pragma unroll
    for (int s = 0; s < 2; s++) {
        issue_stage<KDIM>(Ag, Bg, s * 64, rendRel,
                          sb + s * STAGE_BYTES, sb + s * STAGE_BYTES + 16384, tid);
        cp_commit();
    }

    int s_c = 0, s_p = 2;  // compute stage idx, produce stage idx (mod 3)
#pragma unroll 1
    for (int i = 0; i < CH; i++) {
        cp_wait<1>();
        __syncthreads();
        if (i + 2 < CH) {
            issue_stage<KDIM>(Ag, Bg, (i + 2) * 64, rendRel,
                              sb + s_p * STAGE_BYTES, sb + s_p * STAGE_BYTES + 16384, tid);
        }
        cp_commit();   // uniform commit keeps wait<1> aligned near the tail
        compute_stage64(sb + s_c * STAGE_BYTES, sb + s_c * STAGE_BYTES + 16384, c, wm, wn);
        __syncthreads();
        s_c = (s_c == 2) ? 0 : s_c + 1;
        s_p = (s_p == 2) ? 0 : s_p + 1;
    }

    // ---------------- epilogue ----------------
    if (!SECOND) {
#pragma unroll
        for (int ni = 0; ni < 8; ni++) {
            int col = n0 + wn * 64 + ni * 8 + 2 * tg;
            float bi0 = __ldg(&brow[wn * 64 + ni * 8 + 2 * tg]);
            float bi1 = __ldg(&brow[wn * 64 + ni * 8 + 2 * tg + 1]);
#pragma unroll
            for (int mi = 0; mi < 2; mi++) {
                int r = row0 + wm * 32 + mi * 16 + g;
                *(__half2*)(g_h1h + (size_t)r * F_ + col) =
                    __floats2half2_rn(fmaxf(c[mi][ni][0] + bi0, 0.f),
                                      fmaxf(c[mi][ni][1] + bi1, 0.f));
                *(__half2*)(g_h1h + (size_t)(r + 8) * F_ + col) =
                    __floats2half2_rn(fmaxf(c[mi][ni][2] + bi0, 0.f),
                                      fmaxf(c[mi][ni][3] + bi1, 0.f));
            }
        }
    } else {
#pragma unroll
        for (int ni = 0; ni < 8; ni++) {
            int col = n0 + wn * 64 + ni * 8 + 2 * tg;
            float bi0 = __ldg(&brow[wn * 64 + ni * 8 + 2 * tg]);
            float bi1 = __ldg(&brow[wn * 64 + ni * 8 + 2 * tg + 1]);
#pragma unroll
            for (int mi = 0; mi < 2; mi++) {
                int r = row0 + wm * 32 + mi * 16 + g;
                if (r < rend) {
                    int t = g_srt[r];
                    float al = g_alpha[t];
                    float2 xv = *(const float2*)(x + (size_t)t * D_ + col);
                    float2 o;
                    o.x = xv.x + al * (c[mi][ni][0] + bi0);
                    o.y = xv.y + al * (c[mi][ni][1] + bi1);
                    *(float2*)(out + (size_t)t * D_ + col) = o;
                }
                if (r + 8 < rend) {
                    int t = g_srt[r + 8];
                    float al = g_alpha[t];
                    float2 xv = *(const float2*)(x + (size_t)t * D_ + col);
                    float2 o;
                    o.x = xv.x + al * (c[mi][ni][2] + bi0);
                    o.y = xv.y + al * (c[mi][ni][3] + bi1);
                    *(float2*)(out + (size_t)t * D_ + col) = o;
                }
            }
        }
    }
}

// ------------------- launch -------------------
extern "C" void kernel_launch(void* const* d_in, const int* in_sizes, int n_in,
                              void* d_out, int out_size) {
    const float* x    = (const float*)d_in[0];
    const float* cent = (const float*)d_in[1];
    const float* lng  = (const float*)d_in[2];
    const float* lnb  = (const float*)d_in[3];
    const float* w1   = (const float*)d_in[4];
    const float* b1   = (const float*)d_in[5];
    const float* w2   = (const float*)d_in[6];
    const float* b2   = (const float*)d_in[7];
    float* out = (float*)d_out;

    cudaFuncSetAttribute(hgemm<D_, false>, cudaFuncAttributeMaxDynamicSharedMemorySize, SMEM_TOTAL);
    cudaFuncSetAttribute(hgemm<F_, true>,  cudaFuncAttributeMaxDynamicSharedMemorySize, SMEM_TOTAL);

    init_kernel<<<1, 32>>>();
    convert_kernel<<<4096, 256>>>(w1, 0);
    convert_kernel<<<4096, 256>>>(w2, 1);
    routing_kernel<<<T_ / 8, 256>>>(x, cent);
    scan_kernel<<<1, 1>>>();
    scatter_kernel<<<T_ / 256, 256>>>();
    ln_kernel<<<T_, 256>>>(x, lng, lnb);
    hgemm<D_, false><<<dim3(F_ / 128, MAX_TILES), 256, SMEM_TOTAL>>>(b1, nullptr, nullptr);
    hgemm<F_, true><<<dim3(D_ / 128, MAX_TILES), 256, SMEM_TOTAL>>>(b2, x, out);
}